// round 1
// baseline (speedup 1.0000x reference)
#include <cuda_runtime.h>
#include <cstdint>

// ---------------------------------------------------------------------------
// SparseAttention: x -> qkv proj -> per-offset banded block attention -> proj
// B=8, N=8192, C=512, heads=8 (dh=64), BLOCK=32, WINDOW=64 blocks, nb=256
// ---------------------------------------------------------------------------

static constexpr int B_   = 8;
static constexpr int N_   = 8192;
static constexpr int C_   = 512;
static constexpr int TOK  = B_ * N_;        // 65536
static constexpr int NB   = 256;            // blocks per sequence
static constexpr int SBLK = 32;             // tokens per block
static constexpr int WND  = 64;             // window radius in blocks

// Scratch (device globals: allocation-free per harness rules)
__device__ float g_q[(size_t)TOK * C_];
__device__ float g_k[(size_t)TOK * C_];
__device__ float g_v[(size_t)TOK * C_];
__device__ float g_o[(size_t)TOK * C_];

// ---------------------------------------------------------------------------
// fp32 GEMM: C[M,N] = A[M,K] @ W[K,N] + bias
// 128x128 tile, BK=16, 256 threads, 8x8 per-thread, double-buffered smem.
// MODE 0: plain -> Cout
// MODE 1: qkv scatter -> g_q/g_k/g_v with head-interleave split
// MODE 2: plain, but A is g_o (device global)
// ---------------------------------------------------------------------------
template <int MODE>
__global__ void __launch_bounds__(256, 2)
gemm_f32(const float* __restrict__ A, const float* __restrict__ Bw,
         const float* __restrict__ bias, float* __restrict__ Cout,
         int M, int N, int K)
{
    __shared__ float As[2][16][128];
    __shared__ float Bs[2][16][128];

    const float* Aeff = (MODE == 2) ? (const float*)g_o : A;

    const int tid = threadIdx.x;
    const int bm  = blockIdx.y;
    const int bn  = blockIdx.x;

    const float* Ab = Aeff + (size_t)bm * 128 * K;
    const float* Bb = Bw   + (size_t)bn * 128;

    const int arow = tid >> 2;          // 0..63
    const int acol = (tid & 3) << 2;    // 0,4,8,12
    const int brow = tid >> 5;          // 0..7
    const int bcol = (tid & 31) << 2;   // 0..124

    float4 pa0, pa1, pb0, pb1;

    auto fetch = [&](int k0) {
        pa0 = *(const float4*)(Ab + (size_t)arow        * K + k0 + acol);
        pa1 = *(const float4*)(Ab + (size_t)(arow + 64) * K + k0 + acol);
        pb0 = *(const float4*)(Bb + (size_t)(k0 + brow    ) * N + bcol);
        pb1 = *(const float4*)(Bb + (size_t)(k0 + brow + 8) * N + bcol);
    };
    auto store_smem = [&](int buf) {
        As[buf][acol + 0][arow]      = pa0.x;
        As[buf][acol + 1][arow]      = pa0.y;
        As[buf][acol + 2][arow]      = pa0.z;
        As[buf][acol + 3][arow]      = pa0.w;
        As[buf][acol + 0][arow + 64] = pa1.x;
        As[buf][acol + 1][arow + 64] = pa1.y;
        As[buf][acol + 2][arow + 64] = pa1.z;
        As[buf][acol + 3][arow + 64] = pa1.w;
        *(float4*)&Bs[buf][brow    ][bcol] = pb0;
        *(float4*)&Bs[buf][brow + 8][bcol] = pb1;
    };

    fetch(0);
    store_smem(0);
    __syncthreads();

    const int tx = tid & 15;
    const int ty = tid >> 4;

    float acc[8][8];
    #pragma unroll
    for (int i = 0; i < 8; ++i)
        #pragma unroll
        for (int j = 0; j < 8; ++j) acc[i][j] = 0.f;

    const int nk = K >> 4;
    for (int kt = 0; kt < nk; ++kt) {
        const int cur = kt & 1;
        if (kt + 1 < nk) fetch((kt + 1) << 4);

        #pragma unroll
        for (int kk = 0; kk < 16; ++kk) {
            float ra[8], rb[8];
            *(float4*)&ra[0] = *(const float4*)&As[cur][kk][ty * 8];
            *(float4*)&ra[4] = *(const float4*)&As[cur][kk][ty * 8 + 4];
            *(float4*)&rb[0] = *(const float4*)&Bs[cur][kk][tx * 8];
            *(float4*)&rb[4] = *(const float4*)&Bs[cur][kk][tx * 8 + 4];
            #pragma unroll
            for (int i = 0; i < 8; ++i)
                #pragma unroll
                for (int j = 0; j < 8; ++j)
                    acc[i][j] += ra[i] * rb[j];
        }

        if (kt + 1 < nk) store_smem(cur ^ 1);
        __syncthreads();
    }

    // Epilogue
    const int row0 = bm * 128 + ty * 8;
    const int col0 = bn * 128 + tx * 8;

    #pragma unroll
    for (int jj = 0; jj < 8; jj += 4) {
        const int c = col0 + jj;
        float4 bz = *(const float4*)(bias + c);

        float* dst;
        int    dcol;
        if (MODE == 1) {
            // col c -> head hi = c/192, r = c%192; seg 0/1/2 -> q/k/v, ch = hi*64 + r%64
            const int hi  = c / 192;
            const int rr  = c - hi * 192;
            const int seg = rr >> 6;
            dcol = hi * 64 + (rr & 63);
            dst  = (seg == 0) ? g_q : (seg == 1) ? g_k : g_v;
        } else {
            dst  = Cout;
            dcol = c;
        }
        const int dstride = (MODE == 1) ? 512 : N;

        #pragma unroll
        for (int i = 0; i < 8; ++i) {
            float4 v;
            v.x = acc[i][jj + 0] + bz.x;
            v.y = acc[i][jj + 1] + bz.y;
            v.z = acc[i][jj + 2] + bz.z;
            v.w = acc[i][jj + 3] + bz.w;
            *(float4*)&dst[(size_t)(row0 + i) * dstride + dcol] = v;
        }
    }
}

// ---------------------------------------------------------------------------
// Banded per-offset attention.
// For each (b, s): queries i in [0,256), keys j in [i-64, i+64], dim 512.
// CTA: 16 queries (one (b,s)), 256 threads. Key chunks of 16.
// Thread (qi = tid/16, ks = tid%16):
//   QK phase: computes score (qi, ks) as a full 512-dim dot from smem.
//   PV phase: ks acts as dim-slot; owns float4s d/4 == ks (mod 16) -> 8 float4.
// Online softmax with masked scores at -1e30 and explicit p=0 guard.
// ---------------------------------------------------------------------------
static constexpr int QT = 16;
static constexpr int KT = 16;
static constexpr int KS = 516;              // padded K/V smem row stride (floats)
static constexpr int ATTN_SMEM_FLOATS = QT * C_ + 2 * KT * KS + 2 * QT * 17;
static constexpr int ATTN_SMEM_BYTES  = ATTN_SMEM_FLOATS * 4;   // 100992

__global__ void __launch_bounds__(256, 2)
attn_kernel()
{
    extern __shared__ float sm[];
    float* Qs = sm;                         // 16 * 512
    float* Ks = Qs + QT * C_;               // 16 * 516
    float* Vs = Ks + KT * KS;               // 16 * 516
    float* Ss = Vs + KT * KS;               // 16 * 17
    float* Ps = Ss + QT * 17;               // 16 * 17

    const int tid = threadIdx.x;
    const int i0  = blockIdx.x * QT;        // first query block index
    const int s   = blockIdx.y;             // offset within block, 0..31
    const int b   = blockIdx.z;

    const size_t base = (size_t)b * N_ * C_;

    // Load Q tile: 16 rows x 512 floats = 2048 float4
    #pragma unroll
    for (int p = 0; p < 8; ++p) {
        const int idx = tid + p * 256;
        const int r   = idx >> 7;
        const int f   = (idx & 127) << 2;
        *(float4*)&Qs[r * C_ + f] =
            *(const float4*)(g_q + base + (size_t)((i0 + r) * SBLK + s) * C_ + f);
    }

    const int qi = tid >> 4;
    const int ks = tid & 15;
    const int iq = i0 + qi;

    float m = -1e30f, l = 0.f;
    float4 acc[8];
    #pragma unroll
    for (int z = 0; z < 8; ++z) acc[z] = make_float4(0.f, 0.f, 0.f, 0.f);

    int jlo = i0 - WND;            if (jlo < 0) jlo = 0;
    int jhi = i0 + QT - 1 + WND;   if (jhi > NB - 1) jhi = NB - 1;
    // jlo and jhi+1 are always multiples of 16 -> no ragged chunks.

    const float scale = 0.125f;    // dh^-0.5 = 64^-0.5

    for (int jc = jlo; jc <= jhi; jc += KT) {
        __syncthreads();   // all PV reads of Vs/Ps from prev iter done

        // Load K,V chunk: 16 rows x 512 floats each
        #pragma unroll
        for (int p = 0; p < 8; ++p) {
            const int idx = tid + p * 256;
            const int r   = idx >> 7;
            const int f   = (idx & 127) << 2;
            const size_t g = base + (size_t)((jc + r) * SBLK + s) * C_ + f;
            *(float4*)&Ks[r * KS + f] = *(const float4*)(g_k + g);
            *(float4*)&Vs[r * KS + f] = *(const float4*)(g_v + g);
        }
        __syncthreads();

        // Score (qi, jc+ks)
        const int  j     = jc + ks;
        const bool valid = (j >= iq - WND) && (j <= iq + WND);
        float sc = -1e30f;
        {
            float sum = 0.f;
            const float4* qrow = (const float4*)&Qs[qi * C_];
            const float4* krow = (const float4*)&Ks[ks * KS];
            #pragma unroll 8
            for (int d4 = 0; d4 < 128; ++d4) {
                const float4 a  = qrow[d4];
                const float4 bk = krow[d4];
                sum += a.x * bk.x + a.y * bk.y + a.z * bk.z + a.w * bk.w;
            }
            if (valid) sc = sum * scale;
        }
        Ss[qi * 17 + ks] = sc;
        __syncthreads();

        // Row max (redundant per thread, deterministic)
        float mnew = m;
        #pragma unroll
        for (int k = 0; k < KT; ++k) mnew = fmaxf(mnew, Ss[qi * 17 + k]);

        const float p_own = valid ? __expf(sc - mnew) : 0.f;
        Ps[qi * 17 + ks] = p_own;
        const float corr = __expf(m - mnew);
        m = mnew;
        __syncthreads();

        float lsum = 0.f;
        #pragma unroll
        for (int k = 0; k < KT; ++k) lsum += Ps[qi * 17 + k];
        l = l * corr + lsum;

        #pragma unroll
        for (int z = 0; z < 8; ++z) {
            acc[z].x *= corr; acc[z].y *= corr;
            acc[z].z *= corr; acc[z].w *= corr;
        }
        #pragma unroll
        for (int k = 0; k < KT; ++k) {
            const float p = Ps[qi * 17 + k];
            const float4* vrow = (const float4*)&Vs[k * KS];
            #pragma unroll
            for (int z = 0; z < 8; ++z) {
                const float4 v = vrow[ks + 16 * z];
                acc[z].x += p * v.x; acc[z].y += p * v.y;
                acc[z].z += p * v.z; acc[z].w += p * v.w;
            }
        }
    }

    // Write output (coalesced: 16 ks-threads cover 64 contiguous floats per z)
    const float inv = 1.f / l;
    float* orow = g_o + base + (size_t)(iq * SBLK + s) * C_;
    #pragma unroll
    for (int z = 0; z < 8; ++z) {
        float4 v;
        v.x = acc[z].x * inv; v.y = acc[z].y * inv;
        v.z = acc[z].z * inv; v.w = acc[z].w * inv;
        *(float4*)&orow[(ks + 16 * z) * 4] = v;
    }
}

// ---------------------------------------------------------------------------
extern "C" void kernel_launch(void* const* d_in, const int* in_sizes, int n_in,
                              void* d_out, int out_size)
{
    const float* x     = (const float*)d_in[0];
    const float* Wqkv  = (const float*)d_in[1];
    const float* bqkv  = (const float*)d_in[2];
    const float* Wproj = (const float*)d_in[3];
    const float* bproj = (const float*)d_in[4];
    float*       out   = (float*)d_out;

    // 1) QKV projection + head-interleaved split into g_q/g_k/g_v
    gemm_f32<1><<<dim3(12, 512), 256>>>(x, Wqkv, bqkv, nullptr, TOK, 3 * C_, C_);

    // 2) Banded per-offset attention: g_q,g_k,g_v -> g_o
    cudaFuncSetAttribute(attn_kernel,
                         cudaFuncAttributeMaxDynamicSharedMemorySize,
                         ATTN_SMEM_BYTES);
    attn_kernel<<<dim3(NB / QT, SBLK, B_), 256, ATTN_SMEM_BYTES>>>();

    // 3) Output projection: g_o @ Wproj + bproj -> out
    gemm_f32<2><<<dim3(4, 512), 256>>>(nullptr, Wproj, bproj, out, TOK, C_, C_);
}

// round 4
// speedup vs baseline: 1.7039x; 1.7039x over previous
#include <cuda_runtime.h>
#include <cuda_bf16.h>
#include <cstdint>

// ---------------------------------------------------------------------------
// SparseAttention: x -> qkv proj -> per-offset banded block attention -> proj
// B=8, N=8192, C=512, heads=8 (dh=64), BLOCK=32, WINDOW=64 blocks, nb=256
// GEMMs: mma.sync bf16 (2-way split, 3 MMA products) — arch-agnostic PTX.
// ---------------------------------------------------------------------------

static constexpr int B_   = 8;
static constexpr int N_   = 8192;
static constexpr int C_   = 512;
static constexpr int TOK  = B_ * N_;        // 65536
static constexpr int NB   = 256;
static constexpr int SBLK = 32;
static constexpr int WND  = 64;

// Scratch (device globals: allocation-free per harness rules)
__device__ float g_q[(size_t)TOK * C_];
__device__ float g_k[(size_t)TOK * C_];
__device__ float g_v[(size_t)TOK * C_];
__device__ float g_o[(size_t)TOK * C_];

// bf16 split activations
__device__ __nv_bfloat16 g_xh[(size_t)TOK * C_];
__device__ __nv_bfloat16 g_xl[(size_t)TOK * C_];
__device__ __nv_bfloat16 g_oh[(size_t)TOK * C_];
__device__ __nv_bfloat16 g_ol[(size_t)TOK * C_];

// Pre-transposed / permuted / bf16-split weights + permuted qkv bias
__device__ __nv_bfloat16 g_wtq_hi[3 * C_ * C_];   // [1536 perm][512] K-major
__device__ __nv_bfloat16 g_wtq_lo[3 * C_ * C_];
__device__ __nv_bfloat16 g_wtp_hi[C_ * C_];       // [512][512]
__device__ __nv_bfloat16 g_wtp_lo[C_ * C_];
__device__ float g_bq[3 * C_];

// ---------------------------------------------------------------------------
// helpers
// ---------------------------------------------------------------------------
__device__ __forceinline__ uint32_t smem_u32(const void* p) {
    uint32_t a;
    asm("{ .reg .u64 t; cvta.to.shared.u64 t, %1; cvt.u32.u64 %0, t; }"
        : "=r"(a) : "l"(p));
    return a;
}

__device__ __forceinline__ void cp_async16(uint32_t dst, const void* src) {
    asm volatile("cp.async.cg.shared.global [%0], [%1], 16;"
                 :: "r"(dst), "l"(src) : "memory");
}
__device__ __forceinline__ void cp_commit() {
    asm volatile("cp.async.commit_group;" ::: "memory");
}
__device__ __forceinline__ void cp_wait1() {
    asm volatile("cp.async.wait_group 1;" ::: "memory");
}
__device__ __forceinline__ void cp_wait0() {
    asm volatile("cp.async.wait_group 0;" ::: "memory");
}

__device__ __forceinline__ void ldsm_x4(uint32_t* r, uint32_t addr) {
    asm volatile("ldmatrix.sync.aligned.m8n8.x4.shared.b16 {%0,%1,%2,%3}, [%4];"
                 : "=r"(r[0]), "=r"(r[1]), "=r"(r[2]), "=r"(r[3]) : "r"(addr));
}
__device__ __forceinline__ void ldsm_x2(uint32_t* r, uint32_t addr) {
    asm volatile("ldmatrix.sync.aligned.m8n8.x2.shared.b16 {%0,%1}, [%2];"
                 : "=r"(r[0]), "=r"(r[1]) : "r"(addr));
}

__device__ __forceinline__ void mma_bf16(float* d, const uint32_t* a, const uint32_t* b) {
    asm volatile(
        "mma.sync.aligned.m16n8k16.row.col.f32.bf16.bf16.f32 "
        "{%0,%1,%2,%3}, {%4,%5,%6,%7}, {%8,%9}, {%0,%1,%2,%3};"
        : "+f"(d[0]), "+f"(d[1]), "+f"(d[2]), "+f"(d[3])
        : "r"(a[0]), "r"(a[1]), "r"(a[2]), "r"(a[3]), "r"(b[0]), "r"(b[1]));
}

// ---------------------------------------------------------------------------
// fp32 -> bf16 hi/lo split (elementwise). SRC 0: x (arg). SRC 1: g_o.
// Writes g_xh/g_xl or g_oh/g_ol directly (no symbol-address API needed).
// ---------------------------------------------------------------------------
template <int SRC>
__global__ void split_bf16(const float* __restrict__ xarg)
{
    const float* src = (SRC == 0) ? xarg : (const float*)g_o;
    __nv_bfloat16* hi = (SRC == 0) ? g_xh : g_oh;
    __nv_bfloat16* lo = (SRC == 0) ? g_xl : g_ol;

    const size_t i = ((size_t)blockIdx.x * blockDim.x + threadIdx.x) * 4;
    const float4 v = *(const float4*)(src + i);
    __nv_bfloat16 hx = __float2bfloat16_rn(v.x);
    __nv_bfloat16 hy = __float2bfloat16_rn(v.y);
    __nv_bfloat16 hz = __float2bfloat16_rn(v.z);
    __nv_bfloat16 hw = __float2bfloat16_rn(v.w);
    __nv_bfloat162 h0; h0.x = hx; h0.y = hy;
    __nv_bfloat162 h1; h1.x = hz; h1.y = hw;
    __nv_bfloat162 l0, l1;
    l0.x = __float2bfloat16_rn(v.x - __bfloat162float(hx));
    l0.y = __float2bfloat16_rn(v.y - __bfloat162float(hy));
    l1.x = __float2bfloat16_rn(v.z - __bfloat162float(hz));
    l1.y = __float2bfloat16_rn(v.w - __bfloat162float(hw));
    *(__nv_bfloat162*)(hi + i)     = h0;
    *(__nv_bfloat162*)(hi + i + 2) = h1;
    *(__nv_bfloat162*)(lo + i)     = l0;
    *(__nv_bfloat162*)(lo + i + 2) = l1;
}

// ---------------------------------------------------------------------------
// Weight prep: transpose [K,N]->[N,K], (qkv: permute cols), split to bf16
// ---------------------------------------------------------------------------
__global__ void transpose_qkv(const float* __restrict__ W) {
    __shared__ float t[32][33];
    const int c0 = blockIdx.x * 32;
    const int k0 = blockIdx.y * 32;
    const int tx = threadIdx.x, ty = threadIdx.y;
    #pragma unroll
    for (int i = 0; i < 32; i += 8)
        t[ty + i][tx] = W[(size_t)(k0 + ty + i) * 1536 + c0 + tx];
    __syncthreads();
    #pragma unroll
    for (int i = 0; i < 32; i += 8) {
        const int c  = c0 + ty + i;
        const int hd = c / 192;
        const int rr = c - hd * 192;
        const int cp = (rr >> 6) * 512 + hd * 64 + (rr & 63);
        const float v = t[tx][ty + i];
        const __nv_bfloat16 h = __float2bfloat16_rn(v);
        g_wtq_hi[(size_t)cp * 512 + k0 + tx] = h;
        g_wtq_lo[(size_t)cp * 512 + k0 + tx] =
            __float2bfloat16_rn(v - __bfloat162float(h));
    }
}

__global__ void transpose_proj(const float* __restrict__ W) {
    __shared__ float t[32][33];
    const int c0 = blockIdx.x * 32;
    const int k0 = blockIdx.y * 32;
    const int tx = threadIdx.x, ty = threadIdx.y;
    #pragma unroll
    for (int i = 0; i < 32; i += 8)
        t[ty + i][tx] = W[(size_t)(k0 + ty + i) * 512 + c0 + tx];
    __syncthreads();
    #pragma unroll
    for (int i = 0; i < 32; i += 8) {
        const int c = c0 + ty + i;
        const float v = t[tx][ty + i];
        const __nv_bfloat16 h = __float2bfloat16_rn(v);
        g_wtp_hi[(size_t)c * 512 + k0 + tx] = h;
        g_wtp_lo[(size_t)c * 512 + k0 + tx] =
            __float2bfloat16_rn(v - __bfloat162float(h));
    }
}

__global__ void perm_bias(const float* __restrict__ b) {
    const int c = blockIdx.x * 512 + threadIdx.x;
    if (c < 1536) {
        const int hd = c / 192;
        const int rr = c - hd * 192;
        g_bq[(rr >> 6) * 512 + hd * 64 + (rr & 63)] = b[c];
    }
}

// ---------------------------------------------------------------------------
// bf16 mma.sync GEMM with 2-way split: C = Ah*Bh + Ah*Bl + Al*Bh (+ bias)
// BM=128, BN=128, BK=32, 256 threads (2x4 warps, 64x32 per warp).
// Double-buffered cp.async. Smem rows padded to 40 bf16 (80B stride).
// MODE 1: A = g_xh/g_xl, B = g_wtq_*, out -> g_q/g_k/g_v (+ g_bq)
// MODE 2: A = g_oh/g_ol, B = g_wtp_*, out -> Cout (+ bias)
// ---------------------------------------------------------------------------
static constexpr int GS      = 40;                // smem row stride in bf16
static constexpr int MAT_B   = 128 * GS * 2;      // 10240 bytes per split-matrix
static constexpr int BUF_B   = 4 * MAT_B;         // 40960 per stage
static constexpr int GT_SMEM = 2 * BUF_B + 512;   // 82432

template <int MODE>
__global__ void __launch_bounds__(256, 2)
gemm_mma(const float* __restrict__ bias, float* __restrict__ Cout)
{
    extern __shared__ char smem[];
    const uint32_t sb = smem_u32(smem);
    float* sbias = (float*)(smem + 2 * BUF_B);

    const int tid  = threadIdx.x;
    const int wid  = tid >> 5;
    const int lane = tid & 31;
    const int wm   = wid >> 2;          // 0..1
    const int wn   = wid & 3;           // 0..3
    const int bn   = blockIdx.x;
    const int bm   = blockIdx.y;
    const int n0   = bn * 128;
    const int m0g  = bm * 128;

    const __nv_bfloat16* Ah = (MODE == 1) ? g_xh : g_oh;
    const __nv_bfloat16* Al = (MODE == 1) ? g_xl : g_ol;
    const __nv_bfloat16* Bh = (MODE == 1) ? g_wtq_hi : g_wtp_hi;
    const __nv_bfloat16* Bl = (MODE == 1) ? g_wtq_lo : g_wtp_lo;

    if (tid < 128) {
        const float* bptr = (MODE == 1) ? (const float*)g_bq : bias;
        sbias[tid] = bptr[n0 + tid];
    }

    // cp.async transfer map: idx in [0,2048): mat(2b) | r(7b) | f(2b)
    const auto issue = [&](int kt, int buf) {
        const int kc = kt << 5;
        #pragma unroll
        for (int p = 0; p < 8; ++p) {
            const int idx = tid + (p << 8);
            const int mat = idx >> 9;             // 0:Ah 1:Al 2:Bh 3:Bl
            const int rem = idx & 511;
            const int r   = rem >> 2;             // 0..127
            const int f   = (rem & 3) << 3;       // 0,8,16,24 (bf16)
            const __nv_bfloat16* src;
            if      (mat == 0) src = Ah + (size_t)(m0g + r) * 512 + kc + f;
            else if (mat == 1) src = Al + (size_t)(m0g + r) * 512 + kc + f;
            else if (mat == 2) src = Bh + (size_t)(n0  + r) * 512 + kc + f;
            else               src = Bl + (size_t)(n0  + r) * 512 + kc + f;
            cp_async16(sb + buf * BUF_B + mat * MAT_B + r * (GS * 2) + f * 2, src);
        }
        cp_commit();
    };

    float acc[4][4][4];
    #pragma unroll
    for (int i = 0; i < 4; ++i)
        #pragma unroll
        for (int j = 0; j < 4; ++j)
            #pragma unroll
            for (int z = 0; z < 4; ++z) acc[i][j][z] = 0.f;

    issue(0, 0);

    const int nk = 16;                   // K=512 / 32
    for (int kt = 0; kt < nk; ++kt) {
        const int cur = kt & 1;
        if (kt + 1 < nk) { issue(kt + 1, cur ^ 1); cp_wait1(); }
        else             { cp_wait0(); }
        __syncthreads();

        const uint32_t base = sb + cur * BUF_B;
        #pragma unroll
        for (int k16 = 0; k16 < 32; k16 += 16) {
            uint32_t ah[4][4], al[4][4];
            #pragma unroll
            for (int mt = 0; mt < 4; ++mt) {
                const uint32_t addr = base
                    + (uint32_t)((wm * 64 + mt * 16 + (lane & 15)) * (GS * 2))
                    + (uint32_t)((k16 + ((lane >> 4) << 3)) * 2);
                ldsm_x4(ah[mt], addr);
                ldsm_x4(al[mt], addr + MAT_B);
            }
            #pragma unroll
            for (int nt = 0; nt < 4; ++nt) {
                uint32_t bh[2], bl[2];
                const uint32_t baddr = base + 2 * MAT_B
                    + (uint32_t)((wn * 32 + nt * 8 + (lane & 7)) * (GS * 2))
                    + (uint32_t)((k16 + (((lane >> 3) & 1) << 3)) * 2);
                ldsm_x2(bh, baddr);
                ldsm_x2(bl, baddr + MAT_B);
                #pragma unroll
                for (int mt = 0; mt < 4; ++mt) {
                    mma_bf16(acc[mt][nt], ah[mt], bh);
                    mma_bf16(acc[mt][nt], ah[mt], bl);
                    mma_bf16(acc[mt][nt], al[mt], bh);
                }
            }
        }
        __syncthreads();
    }

    // Epilogue
    float* dst;
    int col0;
    if (MODE == 1) {
        const int seg = n0 >> 9;
        dst  = (seg == 0) ? g_q : (seg == 1) ? g_k : g_v;
        col0 = n0 & 511;
    } else {
        dst  = Cout;
        col0 = n0;
    }

    #pragma unroll
    for (int mt = 0; mt < 4; ++mt) {
        #pragma unroll
        for (int nt = 0; nt < 4; ++nt) {
            const int cb = wn * 32 + nt * 8 + (lane & 3) * 2;
            const int r0 = m0g + wm * 64 + mt * 16 + (lane >> 2);
            float2 v0, v1;
            v0.x = acc[mt][nt][0] + sbias[cb];
            v0.y = acc[mt][nt][1] + sbias[cb + 1];
            v1.x = acc[mt][nt][2] + sbias[cb];
            v1.y = acc[mt][nt][3] + sbias[cb + 1];
            *(float2*)(dst + (size_t)r0 * 512 + col0 + cb)       = v0;
            *(float2*)(dst + (size_t)(r0 + 8) * 512 + col0 + cb) = v1;
        }
    }
}

// ---------------------------------------------------------------------------
// Banded per-offset attention (unchanged — passed correctness in round 1).
// ---------------------------------------------------------------------------
static constexpr int QT = 16;
static constexpr int KT = 16;
static constexpr int KS = 516;
static constexpr int ATTN_SMEM_FLOATS = QT * C_ + 2 * KT * KS + 2 * QT * 17;
static constexpr int ATTN_SMEM_BYTES  = ATTN_SMEM_FLOATS * 4;

__global__ void __launch_bounds__(256, 2)
attn_kernel()
{
    extern __shared__ float sm[];
    float* Qs = sm;
    float* Ks = Qs + QT * C_;
    float* Vs = Ks + KT * KS;
    float* Ss = Vs + KT * KS;
    float* Ps = Ss + QT * 17;

    const int tid = threadIdx.x;
    const int i0  = blockIdx.x * QT;
    const int s   = blockIdx.y;
    const int b   = blockIdx.z;

    const size_t base = (size_t)b * N_ * C_;

    #pragma unroll
    for (int p = 0; p < 8; ++p) {
        const int idx = tid + p * 256;
        const int r   = idx >> 7;
        const int f   = (idx & 127) << 2;
        *(float4*)&Qs[r * C_ + f] =
            *(const float4*)(g_q + base + (size_t)((i0 + r) * SBLK + s) * C_ + f);
    }

    const int qi = tid >> 4;
    const int ks = tid & 15;
    const int iq = i0 + qi;

    float m = -1e30f, l = 0.f;
    float4 acc[8];
    #pragma unroll
    for (int z = 0; z < 8; ++z) acc[z] = make_float4(0.f, 0.f, 0.f, 0.f);

    int jlo = i0 - WND;            if (jlo < 0) jlo = 0;
    int jhi = i0 + QT - 1 + WND;   if (jhi > NB - 1) jhi = NB - 1;

    const float scale = 0.125f;

    for (int jc = jlo; jc <= jhi; jc += KT) {
        __syncthreads();

        #pragma unroll
        for (int p = 0; p < 8; ++p) {
            const int idx = tid + p * 256;
            const int r   = idx >> 7;
            const int f   = (idx & 127) << 2;
            const size_t g = base + (size_t)((jc + r) * SBLK + s) * C_ + f;
            *(float4*)&Ks[r * KS + f] = *(const float4*)(g_k + g);
            *(float4*)&Vs[r * KS + f] = *(const float4*)(g_v + g);
        }
        __syncthreads();

        const int  j     = jc + ks;
        const bool valid = (j >= iq - WND) && (j <= iq + WND);
        float sc = -1e30f;
        {
            float sum = 0.f;
            const float4* qrow = (const float4*)&Qs[qi * C_];
            const float4* krow = (const float4*)&Ks[ks * KS];
            #pragma unroll 8
            for (int d4 = 0; d4 < 128; ++d4) {
                const float4 a  = qrow[d4];
                const float4 bk = krow[d4];
                sum += a.x * bk.x + a.y * bk.y + a.z * bk.z + a.w * bk.w;
            }
            if (valid) sc = sum * scale;
        }
        Ss[qi * 17 + ks] = sc;
        __syncthreads();

        float mnew = m;
        #pragma unroll
        for (int k = 0; k < KT; ++k) mnew = fmaxf(mnew, Ss[qi * 17 + k]);

        const float p_own = valid ? __expf(sc - mnew) : 0.f;
        Ps[qi * 17 + ks] = p_own;
        const float corr = __expf(m - mnew);
        m = mnew;
        __syncthreads();

        float lsum = 0.f;
        #pragma unroll
        for (int k = 0; k < KT; ++k) lsum += Ps[qi * 17 + k];
        l = l * corr + lsum;

        #pragma unroll
        for (int z = 0; z < 8; ++z) {
            acc[z].x *= corr; acc[z].y *= corr;
            acc[z].z *= corr; acc[z].w *= corr;
        }
        #pragma unroll
        for (int k = 0; k < KT; ++k) {
            const float p = Ps[qi * 17 + k];
            const float4* vrow = (const float4*)&Vs[k * KS];
            #pragma unroll
            for (int z = 0; z < 8; ++z) {
                const float4 v = vrow[ks + 16 * z];
                acc[z].x += p * v.x; acc[z].y += p * v.y;
                acc[z].z += p * v.z; acc[z].w += p * v.w;
            }
        }
    }

    const float inv = 1.f / l;
    float* orow = g_o + base + (size_t)(iq * SBLK + s) * C_;
    #pragma unroll
    for (int z = 0; z < 8; ++z) {
        float4 v;
        v.x = acc[z].x * inv; v.y = acc[z].y * inv;
        v.z = acc[z].z * inv; v.w = acc[z].w * inv;
        *(float4*)&orow[(ks + 16 * z) * 4] = v;
    }
}

// ---------------------------------------------------------------------------
extern "C" void kernel_launch(void* const* d_in, const int* in_sizes, int n_in,
                              void* d_out, int out_size)
{
    const float* x     = (const float*)d_in[0];
    const float* Wqkv  = (const float*)d_in[1];
    const float* bqkv  = (const float*)d_in[2];
    const float* Wproj = (const float*)d_in[3];
    const float* bproj = (const float*)d_in[4];
    float*       out   = (float*)d_out;

    // 0) weight prep + input split
    transpose_qkv <<<dim3(48, 16), dim3(32, 8)>>>(Wqkv);
    transpose_proj<<<dim3(16, 16), dim3(32, 8)>>>(Wproj);
    perm_bias<<<3, 512>>>(bqkv);
    split_bf16<0><<<TOK * C_ / 1024, 256>>>(x);

    // 1) QKV projection (bf16 mma, 2-way split) -> g_q/g_k/g_v
    cudaFuncSetAttribute(gemm_mma<1>, cudaFuncAttributeMaxDynamicSharedMemorySize, GT_SMEM);
    gemm_mma<1><<<dim3(12, 512), 256, GT_SMEM>>>(nullptr, nullptr);

    // 2) Banded per-offset attention
    cudaFuncSetAttribute(attn_kernel, cudaFuncAttributeMaxDynamicSharedMemorySize,
                         ATTN_SMEM_BYTES);
    attn_kernel<<<dim3(NB / QT, SBLK, B_), 256, ATTN_SMEM_BYTES>>>();

    // 3) split attention output, then output projection -> out
    split_bf16<1><<<TOK * C_ / 1024, 256>>>(nullptr);
    cudaFuncSetAttribute(gemm_mma<2>, cudaFuncAttributeMaxDynamicSharedMemorySize, GT_SMEM);
    gemm_mma<2><<<dim3(4, 512), 256, GT_SMEM>>>(bproj, out);
}

// round 6
// speedup vs baseline: 2.7453x; 1.6112x over previous
#include <cuda_runtime.h>
#include <cuda_bf16.h>
#include <cstdint>

// ---------------------------------------------------------------------------
// SparseAttention: x -> qkv proj -> banded per-offset block attention -> proj
// B=8, N=8192, C=512, h=8(dh=64), BLOCK=32, WINDOW=64 blocks, nb=256
// Everything on mma.sync bf16 with hi/lo split (arch-agnostic PTX).
// ---------------------------------------------------------------------------

static constexpr int B_  = 8;
static constexpr int N_  = 8192;
static constexpr int C_  = 512;
static constexpr int TOK = B_ * N_;   // 65536

__device__ __nv_bfloat16 g_xh[(size_t)TOK * C_];
__device__ __nv_bfloat16 g_xl[(size_t)TOK * C_];
__device__ __nv_bfloat16 g_qh[(size_t)TOK * C_];
__device__ __nv_bfloat16 g_ql[(size_t)TOK * C_];
__device__ __nv_bfloat16 g_kh[(size_t)TOK * C_];
__device__ __nv_bfloat16 g_kl[(size_t)TOK * C_];
__device__ __nv_bfloat16 g_vh[(size_t)TOK * C_];
__device__ __nv_bfloat16 g_vl[(size_t)TOK * C_];
__device__ __nv_bfloat16 g_oh[(size_t)TOK * C_];
__device__ __nv_bfloat16 g_ol[(size_t)TOK * C_];

__device__ __nv_bfloat16 g_wtq_hi[3 * C_ * C_];
__device__ __nv_bfloat16 g_wtq_lo[3 * C_ * C_];
__device__ __nv_bfloat16 g_wtp_hi[C_ * C_];
__device__ __nv_bfloat16 g_wtp_lo[C_ * C_];
__device__ float g_bq[3 * C_];

// ------------------------------ helpers ------------------------------------
__device__ __forceinline__ uint32_t smem_u32(const void* p) {
    uint32_t a;
    asm("{ .reg .u64 t; cvta.to.shared.u64 t, %1; cvt.u32.u64 %0, t; }"
        : "=r"(a) : "l"(p));
    return a;
}
__device__ __forceinline__ void cp_async16(uint32_t dst, const void* src) {
    asm volatile("cp.async.cg.shared.global [%0], [%1], 16;"
                 :: "r"(dst), "l"(src) : "memory");
}
__device__ __forceinline__ void cp_commit() {
    asm volatile("cp.async.commit_group;" ::: "memory");
}
__device__ __forceinline__ void cp_wait1() {
    asm volatile("cp.async.wait_group 1;" ::: "memory");
}
__device__ __forceinline__ void cp_wait0() {
    asm volatile("cp.async.wait_group 0;" ::: "memory");
}
__device__ __forceinline__ void ldsm_x4(uint32_t* r, uint32_t a) {
    asm volatile("ldmatrix.sync.aligned.m8n8.x4.shared.b16 {%0,%1,%2,%3}, [%4];"
                 : "=r"(r[0]), "=r"(r[1]), "=r"(r[2]), "=r"(r[3]) : "r"(a));
}
__device__ __forceinline__ void ldsm_x2(uint32_t* r, uint32_t a) {
    asm volatile("ldmatrix.sync.aligned.m8n8.x2.shared.b16 {%0,%1}, [%2];"
                 : "=r"(r[0]), "=r"(r[1]) : "r"(a));
}
__device__ __forceinline__ void ldsm_x2t(uint32_t* r, uint32_t a) {
    asm volatile("ldmatrix.sync.aligned.m8n8.x2.trans.shared.b16 {%0,%1}, [%2];"
                 : "=r"(r[0]), "=r"(r[1]) : "r"(a));
}
__device__ __forceinline__ void mma_bf16(float* d, const uint32_t* a, const uint32_t* b) {
    asm volatile(
        "mma.sync.aligned.m16n8k16.row.col.f32.bf16.bf16.f32 "
        "{%0,%1,%2,%3}, {%4,%5,%6,%7}, {%8,%9}, {%0,%1,%2,%3};"
        : "+f"(d[0]), "+f"(d[1]), "+f"(d[2]), "+f"(d[3])
        : "r"(a[0]), "r"(a[1]), "r"(a[2]), "r"(a[3]), "r"(b[0]), "r"(b[1]));
}
__device__ __forceinline__ uint32_t pack2(float a, float b) {
    __nv_bfloat162 t;
    t.x = __float2bfloat16_rn(a); t.y = __float2bfloat16_rn(b);
    return *(uint32_t*)&t;
}
__device__ __forceinline__ void split2(float a, float b, uint32_t& h, uint32_t& l) {
    __nv_bfloat16 ha = __float2bfloat16_rn(a), hb = __float2bfloat16_rn(b);
    h = pack2(a, b);   // pack of rn == pair(ha,hb)
    l = pack2(a - __bfloat162float(ha), b - __bfloat162float(hb));
}

// ------------------------------ prep kernels -------------------------------
__global__ void split_x(const float* __restrict__ src) {
    const size_t i = ((size_t)blockIdx.x * blockDim.x + threadIdx.x) * 4;
    const float4 v = *(const float4*)(src + i);
    uint32_t h0, l0, h1, l1;
    split2(v.x, v.y, h0, l0);
    split2(v.z, v.w, h1, l1);
    *(uint32_t*)(g_xh + i)     = h0;
    *(uint32_t*)(g_xh + i + 2) = h1;
    *(uint32_t*)(g_xl + i)     = l0;
    *(uint32_t*)(g_xl + i + 2) = l1;
}

__global__ void transpose_qkv(const float* __restrict__ W) {
    __shared__ float t[32][33];
    const int c0 = blockIdx.x * 32, k0 = blockIdx.y * 32;
    const int tx = threadIdx.x, ty = threadIdx.y;
    #pragma unroll
    for (int i = 0; i < 32; i += 8)
        t[ty + i][tx] = W[(size_t)(k0 + ty + i) * 1536 + c0 + tx];
    __syncthreads();
    #pragma unroll
    for (int i = 0; i < 32; i += 8) {
        const int c  = c0 + ty + i;
        const int hd = c / 192, rr = c - hd * 192;
        const int cp = (rr >> 6) * 512 + hd * 64 + (rr & 63);
        const float v = t[tx][ty + i];
        const __nv_bfloat16 h = __float2bfloat16_rn(v);
        g_wtq_hi[(size_t)cp * 512 + k0 + tx] = h;
        g_wtq_lo[(size_t)cp * 512 + k0 + tx] =
            __float2bfloat16_rn(v - __bfloat162float(h));
    }
}

__global__ void transpose_proj(const float* __restrict__ W) {
    __shared__ float t[32][33];
    const int c0 = blockIdx.x * 32, k0 = blockIdx.y * 32;
    const int tx = threadIdx.x, ty = threadIdx.y;
    #pragma unroll
    for (int i = 0; i < 32; i += 8)
        t[ty + i][tx] = W[(size_t)(k0 + ty + i) * 512 + c0 + tx];
    __syncthreads();
    #pragma unroll
    for (int i = 0; i < 32; i += 8) {
        const int c = c0 + ty + i;
        const float v = t[tx][ty + i];
        const __nv_bfloat16 h = __float2bfloat16_rn(v);
        g_wtp_hi[(size_t)c * 512 + k0 + tx] = h;
        g_wtp_lo[(size_t)c * 512 + k0 + tx] =
            __float2bfloat16_rn(v - __bfloat162float(h));
    }
}

__global__ void perm_bias(const float* __restrict__ b) {
    const int c = blockIdx.x * 512 + threadIdx.x;
    if (c < 1536) {
        const int hd = c / 192, rr = c - hd * 192;
        g_bq[(rr >> 6) * 512 + hd * 64 + (rr & 63)] = b[c];
    }
}

// ---------------------------------------------------------------------------
// bf16 split GEMM (same as round-4 passing kernel; MODE 1 epilogue -> hi/lo)
// ---------------------------------------------------------------------------
static constexpr int GS      = 40;
static constexpr int MAT_B   = 128 * GS * 2;
static constexpr int BUF_B   = 4 * MAT_B;
static constexpr int GT_SMEM = 2 * BUF_B + 512;

template <int MODE>
__global__ void __launch_bounds__(256, 2)
gemm_mma(const float* __restrict__ bias, float* __restrict__ Cout)
{
    extern __shared__ char smem[];
    const uint32_t sb = smem_u32(smem);
    float* sbias = (float*)(smem + 2 * BUF_B);

    const int tid = threadIdx.x, wid = tid >> 5, lane = tid & 31;
    const int wm = wid >> 2, wn = wid & 3;
    const int n0 = blockIdx.x * 128, m0g = blockIdx.y * 128;

    const __nv_bfloat16* Ah = (MODE == 1) ? g_xh : g_oh;
    const __nv_bfloat16* Al = (MODE == 1) ? g_xl : g_ol;
    const __nv_bfloat16* Bh = (MODE == 1) ? g_wtq_hi : g_wtp_hi;
    const __nv_bfloat16* Bl = (MODE == 1) ? g_wtq_lo : g_wtp_lo;

    if (tid < 128) {
        const float* bptr = (MODE == 1) ? (const float*)g_bq : bias;
        sbias[tid] = bptr[n0 + tid];
    }

    const auto issue = [&](int kt, int buf) {
        const int kc = kt << 5;
        #pragma unroll
        for (int p = 0; p < 8; ++p) {
            const int idx = tid + (p << 8);
            const int mat = idx >> 9;
            const int rem = idx & 511;
            const int r = rem >> 2, f = (rem & 3) << 3;
            const __nv_bfloat16* src;
            if      (mat == 0) src = Ah + (size_t)(m0g + r) * 512 + kc + f;
            else if (mat == 1) src = Al + (size_t)(m0g + r) * 512 + kc + f;
            else if (mat == 2) src = Bh + (size_t)(n0  + r) * 512 + kc + f;
            else               src = Bl + (size_t)(n0  + r) * 512 + kc + f;
            cp_async16(sb + buf * BUF_B + mat * MAT_B + r * (GS * 2) + f * 2, src);
        }
        cp_commit();
    };

    float acc[4][4][4];
    #pragma unroll
    for (int i = 0; i < 4; ++i)
        #pragma unroll
        for (int j = 0; j < 4; ++j)
            #pragma unroll
            for (int z = 0; z < 4; ++z) acc[i][j][z] = 0.f;

    issue(0, 0);
    for (int kt = 0; kt < 16; ++kt) {
        const int cur = kt & 1;
        if (kt + 1 < 16) { issue(kt + 1, cur ^ 1); cp_wait1(); }
        else             { cp_wait0(); }
        __syncthreads();

        const uint32_t base = sb + cur * BUF_B;
        #pragma unroll
        for (int k16 = 0; k16 < 32; k16 += 16) {
            uint32_t ah[4][4], al[4][4];
            #pragma unroll
            for (int mt = 0; mt < 4; ++mt) {
                const uint32_t a = base
                    + (uint32_t)((wm * 64 + mt * 16 + (lane & 15)) * (GS * 2))
                    + (uint32_t)((k16 + ((lane >> 4) << 3)) * 2);
                ldsm_x4(ah[mt], a);
                ldsm_x4(al[mt], a + MAT_B);
            }
            #pragma unroll
            for (int nt = 0; nt < 4; ++nt) {
                uint32_t bh[2], bl[2];
                const uint32_t ba = base + 2 * MAT_B
                    + (uint32_t)((wn * 32 + nt * 8 + (lane & 7)) * (GS * 2))
                    + (uint32_t)((k16 + (((lane >> 3) & 1) << 3)) * 2);
                ldsm_x2(bh, ba);
                ldsm_x2(bl, ba + MAT_B);
                #pragma unroll
                for (int mt = 0; mt < 4; ++mt) {
                    mma_bf16(acc[mt][nt], ah[mt], bh);
                    mma_bf16(acc[mt][nt], ah[mt], bl);
                    mma_bf16(acc[mt][nt], al[mt], bh);
                }
            }
        }
        __syncthreads();
    }

    __nv_bfloat16 *dh = nullptr, *dl = nullptr;
    int col0 = n0;
    if (MODE == 1) {
        const int seg = n0 >> 9;
        dh = (seg == 0) ? g_qh : (seg == 1) ? g_kh : g_vh;
        dl = (seg == 0) ? g_ql : (seg == 1) ? g_kl : g_vl;
        col0 = n0 & 511;
    }
    #pragma unroll
    for (int mt = 0; mt < 4; ++mt) {
        #pragma unroll
        for (int nt = 0; nt < 4; ++nt) {
            const int cb = wn * 32 + nt * 8 + (lane & 3) * 2;
            const int r0 = m0g + wm * 64 + mt * 16 + (lane >> 2);
            const float b0 = sbias[cb], b1 = sbias[cb + 1];
            const float v00 = acc[mt][nt][0] + b0, v01 = acc[mt][nt][1] + b1;
            const float v10 = acc[mt][nt][2] + b0, v11 = acc[mt][nt][3] + b1;
            if (MODE == 1) {
                uint32_t h0, l0, h1, l1;
                split2(v00, v01, h0, l0);
                split2(v10, v11, h1, l1);
                *(uint32_t*)(dh + (size_t)r0 * 512 + col0 + cb)       = h0;
                *(uint32_t*)(dl + (size_t)r0 * 512 + col0 + cb)       = l0;
                *(uint32_t*)(dh + (size_t)(r0 + 8) * 512 + col0 + cb) = h1;
                *(uint32_t*)(dl + (size_t)(r0 + 8) * 512 + col0 + cb) = l1;
            } else {
                float2 f0; f0.x = v00; f0.y = v01;
                float2 f1; f1.x = v10; f1.y = v11;
                *(float2*)(Cout + (size_t)r0 * 512 + col0 + cb)       = f0;
                *(float2*)(Cout + (size_t)(r0 + 8) * 512 + col0 + cb) = f1;
            }
        }
    }
}

// ---------------------------------------------------------------------------
// Flash banded attention on mma.sync (bf16 hi/lo).
// CTA: one (b,s), 32 query blocks; key chunks of 32; 8 warps, 256 threads.
// ---------------------------------------------------------------------------
static constexpr int ARS   = 1040;              // smem row stride bytes
static constexpr int AT_QH = 0;
static constexpr int AT_QL = AT_QH + 32 * ARS;
static constexpr int AT_KH = AT_QL + 32 * ARS;
static constexpr int AT_KL = AT_KH + 32 * ARS;
static constexpr int AT_VH = AT_KL + 32 * ARS;
static constexpr int AT_VL = AT_VH + 32 * ARS;
static constexpr int AT_PH = AT_VL + 32 * ARS;  // 32 x 80B
static constexpr int AT_PL = AT_PH + 32 * 80;
static constexpr int AT_M  = AT_PL + 32 * 80;
static constexpr int AT_L  = AT_M + 128;
static constexpr int AT_C  = AT_L + 128;
static constexpr int AT_PM = AT_C + 128;        // 32*4 f32
static constexpr int AT_PS = AT_PM + 512;
static constexpr int AT_SMEM = AT_PS + 512;     // 206208

__global__ void __launch_bounds__(256, 1)
attn_mma()
{
    extern __shared__ char smem[];
    const uint32_t sb = smem_u32(smem);
    float* sM  = (float*)(smem + AT_M);
    float* sL  = (float*)(smem + AT_L);
    float* sC  = (float*)(smem + AT_C);
    float* sPM = (float*)(smem + AT_PM);
    float* sPS = (float*)(smem + AT_PS);

    const int tid = threadIdx.x, wid = tid >> 5, lane = tid & 31;
    const int qh = wid & 1, ws = wid >> 1;      // ws: QK key-octet / PV c-slice
    const int g = lane >> 2, t = lane & 3;
    const int i0 = blockIdx.x * 32;
    const int s  = blockIdx.y;
    const int bb = blockIdx.z * N_;

    if (tid < 32) { sM[tid] = -1e30f; sL[tid] = 0.f; }

    const int jlo = (i0 - 64 > 0) ? i0 - 64 : 0;
    const int jhe = (i0 + 96 < 256) ? i0 + 96 : 256;
    const int nc  = (jhe - jlo) >> 5;

    const auto load2 = [&](int blk0, uint32_t dh, uint32_t dl,
                           const __nv_bfloat16* gh, const __nv_bfloat16* gl) {
        #pragma unroll
        for (int p = 0; p < 16; ++p) {
            const int idx = tid + (p << 8);
            const int mat = idx >> 11;
            const int rem = idx & 2047;
            const int r = rem >> 6, f = rem & 63;
            const __nv_bfloat16* src = (mat ? gl : gh)
                + ((size_t)(bb + (blk0 + r) * 32 + s) * 512 + f * 8);
            cp_async16((mat ? dl : dh) + r * ARS + f * 16, src);
        }
    };

    load2(i0,  sb + AT_QH, sb + AT_QL, g_qh, g_ql);
    load2(jlo, sb + AT_KH, sb + AT_KL, g_kh, g_kl);
    cp_commit();
    load2(jlo, sb + AT_VH, sb + AT_VL, g_vh, g_vl);
    cp_commit();

    float acc[16][4];
    #pragma unroll
    for (int nt = 0; nt < 16; ++nt)
        #pragma unroll
        for (int z = 0; z < 4; ++z) acc[nt][z] = 0.f;

    const int lr0 = qh * 16 + g, lr1 = lr0 + 8;  // local rows
    const int gq0 = i0 + lr0, gq1 = i0 + lr1;    // global query blocks

    for (int n = 0; n < nc; ++n) {
        const int jc = jlo + n * 32;
        cp_wait1();
        __syncthreads();                          // Q,K(n) ready; stats init ok

        // ---- QK: 16x8 score tile over 512 channels ----
        float sc[4] = {0.f, 0.f, 0.f, 0.f};
        {
            const uint32_t qa = sb + AT_QH + (qh * 16 + (lane & 15)) * ARS
                              + ((lane >> 4) << 4);
            const uint32_t ka = sb + AT_KH + (ws * 8 + (lane & 7)) * ARS
                              + (((lane >> 3) & 1) << 4);
            #pragma unroll 8
            for (int kc = 0; kc < 32; ++kc) {
                uint32_t ah[4], al[4], bh[2], bl[2];
                ldsm_x4(ah, qa + kc * 32);
                ldsm_x4(al, qa + kc * 32 + (AT_QL - AT_QH));
                ldsm_x2(bh, ka + kc * 32);
                ldsm_x2(bl, ka + kc * 32 + (AT_KL - AT_KH));
                mma_bf16(sc, ah, bh);
                mma_bf16(sc, ah, bl);
                mma_bf16(sc, al, bh);
            }
        }

        // scale + mask
        const int cj = jc + ws * 8 + 2 * t;
        const bool m00 = (cj     >= gq0 - 64) && (cj     <= gq0 + 64);
        const bool m01 = (cj + 1 >= gq0 - 64) && (cj + 1 <= gq0 + 64);
        const bool m10 = (cj     >= gq1 - 64) && (cj     <= gq1 + 64);
        const bool m11 = (cj + 1 >= gq1 - 64) && (cj + 1 <= gq1 + 64);
        const float s00 = m00 ? sc[0] * 0.125f : -1e30f;
        const float s01 = m01 ? sc[1] * 0.125f : -1e30f;
        const float s10 = m10 ? sc[2] * 0.125f : -1e30f;
        const float s11 = m11 ? sc[3] * 0.125f : -1e30f;

        // per-warp partial row max (reduce over t lanes)
        float x0 = fmaxf(s00, s01), x1 = fmaxf(s10, s11);
        x0 = fmaxf(x0, __shfl_xor_sync(0xffffffffu, x0, 1));
        x0 = fmaxf(x0, __shfl_xor_sync(0xffffffffu, x0, 2));
        x1 = fmaxf(x1, __shfl_xor_sync(0xffffffffu, x1, 1));
        x1 = fmaxf(x1, __shfl_xor_sync(0xffffffffu, x1, 2));
        if (t == 0) { sPM[lr0 * 4 + ws] = x0; sPM[lr1 * 4 + ws] = x1; }
        __syncthreads();                          // QK done + sPM visible

        if (n + 1 < nc) { load2(jc + 32, sb + AT_KH, sb + AT_KL, g_kh, g_kl); cp_commit(); }

        if (tid < 32) {
            const float mo = sM[tid];
            float mn = fmaxf(fmaxf(sPM[tid * 4], sPM[tid * 4 + 1]),
                             fmaxf(sPM[tid * 4 + 2], sPM[tid * 4 + 3]));
            mn = fmaxf(mn, mo);
            sM[tid] = mn;
            sC[tid] = __expf(mo - mn);
        }
        __syncthreads();                          // sM/sC visible

        // ---- p = exp(s - m); write P hi/lo; partial row sums ----
        const float mn0 = sM[lr0], mn1 = sM[lr1];
        const float p00 = m00 ? __expf(s00 - mn0) : 0.f;
        const float p01 = m01 ? __expf(s01 - mn0) : 0.f;
        const float p10 = m10 ? __expf(s10 - mn1) : 0.f;
        const float p11 = m11 ? __expf(s11 - mn1) : 0.f;
        {
            uint32_t h0, l0, h1, l1;
            split2(p00, p01, h0, l0);
            split2(p10, p11, h1, l1);
            const uint32_t cb = (uint32_t)((ws * 8 + 2 * t) * 2);
            *(uint32_t*)(smem + AT_PH + lr0 * 80 + cb) = h0;
            *(uint32_t*)(smem + AT_PL + lr0 * 80 + cb) = l0;
            *(uint32_t*)(smem + AT_PH + lr1 * 80 + cb) = h1;
            *(uint32_t*)(smem + AT_PL + lr1 * 80 + cb) = l1;
        }
        float r0s = p00 + p01, r1s = p10 + p11;
        r0s += __shfl_xor_sync(0xffffffffu, r0s, 1);
        r0s += __shfl_xor_sync(0xffffffffu, r0s, 2);
        r1s += __shfl_xor_sync(0xffffffffu, r1s, 1);
        r1s += __shfl_xor_sync(0xffffffffu, r1s, 2);
        if (t == 0) { sPS[lr0 * 4 + ws] = r0s; sPS[lr1 * 4 + ws] = r1s; }

        if (n + 1 == nc) cp_wait0(); else cp_wait1();
        __syncthreads();                          // P + V(n) + sPS visible

        if (tid < 32)
            sL[tid] = sL[tid] * sC[tid]
                    + sPS[tid * 4] + sPS[tid * 4 + 1]
                    + sPS[tid * 4 + 2] + sPS[tid * 4 + 3];

        // ---- PV: O(16 x 128-slice) += P * V ----
        const float cr0 = sC[lr0], cr1 = sC[lr1];
        #pragma unroll
        for (int nt = 0; nt < 16; ++nt) {
            acc[nt][0] *= cr0; acc[nt][1] *= cr0;
            acc[nt][2] *= cr1; acc[nt][3] *= cr1;
        }
        {
            const uint32_t pa = sb + AT_PH + (qh * 16 + (lane & 15)) * 80
                              + ((lane >> 4) << 4);
            const uint32_t va = sb + AT_VH + (lane & 15) * ARS
                              + (uint32_t)(ws * 256);
            #pragma unroll
            for (int k2 = 0; k2 < 2; ++k2) {
                uint32_t ph[4], pl[4];
                ldsm_x4(ph, pa + k2 * 32);
                ldsm_x4(pl, pa + k2 * 32 + (AT_PL - AT_PH));
                #pragma unroll
                for (int nt = 0; nt < 16; ++nt) {
                    uint32_t vh2[2], vl2[2];
                    const uint32_t a = va + (uint32_t)(k2 * 16 * ARS) + nt * 16;
                    ldsm_x2t(vh2, a);
                    ldsm_x2t(vl2, a + (AT_VL - AT_VH));
                    mma_bf16(acc[nt], ph, vh2);
                    mma_bf16(acc[nt], ph, vl2);
                    mma_bf16(acc[nt], pl, vh2);
                }
            }
        }
        __syncthreads();                          // PV done reading Vs/Ps

        if (n + 1 < nc) { load2(jc + 32, sb + AT_VH, sb + AT_VL, g_vh, g_vl); cp_commit(); }
    }

    __syncthreads();
    const float inv0 = 1.f / sL[lr0], inv1 = 1.f / sL[lr1];
    const size_t tok0 = (size_t)(bb + gq0 * 32 + s) * 512;
    const size_t tok1 = (size_t)(bb + gq1 * 32 + s) * 512;
    #pragma unroll
    for (int nt = 0; nt < 16; ++nt) {
        const int c = ws * 128 + nt * 8 + 2 * t;
        uint32_t h0, l0, h1, l1;
        split2(acc[nt][0] * inv0, acc[nt][1] * inv0, h0, l0);
        split2(acc[nt][2] * inv1, acc[nt][3] * inv1, h1, l1);
        *(uint32_t*)(g_oh + tok0 + c) = h0;
        *(uint32_t*)(g_ol + tok0 + c) = l0;
        *(uint32_t*)(g_oh + tok1 + c) = h1;
        *(uint32_t*)(g_ol + tok1 + c) = l1;
    }
}

// ---------------------------------------------------------------------------
extern "C" void kernel_launch(void* const* d_in, const int* in_sizes, int n_in,
                              void* d_out, int out_size)
{
    const float* x     = (const float*)d_in[0];
    const float* Wqkv  = (const float*)d_in[1];
    const float* bqkv  = (const float*)d_in[2];
    const float* Wproj = (const float*)d_in[3];
    const float* bproj = (const float*)d_in[4];
    float*       out   = (float*)d_out;

    transpose_qkv <<<dim3(48, 16), dim3(32, 8)>>>(Wqkv);
    transpose_proj<<<dim3(16, 16), dim3(32, 8)>>>(Wproj);
    perm_bias<<<3, 512>>>(bqkv);
    split_x<<<TOK * C_ / 1024, 256>>>(x);

    cudaFuncSetAttribute(gemm_mma<1>, cudaFuncAttributeMaxDynamicSharedMemorySize, GT_SMEM);
    gemm_mma<1><<<dim3(12, 512), 256, GT_SMEM>>>(nullptr, nullptr);

    cudaFuncSetAttribute(attn_mma, cudaFuncAttributeMaxDynamicSharedMemorySize, AT_SMEM);
    attn_mma<<<dim3(8, 32, 8), 256, AT_SMEM>>>();

    cudaFuncSetAttribute(gemm_mma<2>, cudaFuncAttributeMaxDynamicSharedMemorySize, GT_SMEM);
    gemm_mma<2><<<dim3(4, 512), 256, GT_SMEM>>>(bproj, out);
}

// round 7
// speedup vs baseline: 2.7499x; 1.0017x over previous
#include <cuda_runtime.h>
#include <cuda_bf16.h>
#include <cstdint>

// ---------------------------------------------------------------------------
// SparseAttention: x -> qkv proj -> banded per-offset block attention -> proj
// B=8, N=8192, C=512, BLOCK=32, WINDOW=64 blocks, nb=256
// All matmuls on mma.sync bf16 hi/lo split. LDSM minimized via x4 pairing.
// ---------------------------------------------------------------------------

static constexpr int B_  = 8;
static constexpr int N_  = 8192;
static constexpr int C_  = 512;
static constexpr int TOK = B_ * N_;

__device__ __nv_bfloat16 g_xh[(size_t)TOK * C_];
__device__ __nv_bfloat16 g_xl[(size_t)TOK * C_];
__device__ __nv_bfloat16 g_qh[(size_t)TOK * C_];
__device__ __nv_bfloat16 g_ql[(size_t)TOK * C_];
__device__ __nv_bfloat16 g_kh[(size_t)TOK * C_];
__device__ __nv_bfloat16 g_kl[(size_t)TOK * C_];
__device__ __nv_bfloat16 g_vh[(size_t)TOK * C_];
__device__ __nv_bfloat16 g_vl[(size_t)TOK * C_];
__device__ __nv_bfloat16 g_oh[(size_t)TOK * C_];
__device__ __nv_bfloat16 g_ol[(size_t)TOK * C_];

__device__ __nv_bfloat16 g_wtq_hi[3 * C_ * C_];
__device__ __nv_bfloat16 g_wtq_lo[3 * C_ * C_];
__device__ __nv_bfloat16 g_wtp_hi[C_ * C_];
__device__ __nv_bfloat16 g_wtp_lo[C_ * C_];
__device__ float g_bq[3 * C_];

// ------------------------------ helpers ------------------------------------
__device__ __forceinline__ uint32_t smem_u32(const void* p) {
    uint32_t a;
    asm("{ .reg .u64 t; cvta.to.shared.u64 t, %1; cvt.u32.u64 %0, t; }"
        : "=r"(a) : "l"(p));
    return a;
}
__device__ __forceinline__ void cp_async16(uint32_t dst, const void* src) {
    asm volatile("cp.async.cg.shared.global [%0], [%1], 16;"
                 :: "r"(dst), "l"(src) : "memory");
}
__device__ __forceinline__ void cp_commit() {
    asm volatile("cp.async.commit_group;" ::: "memory");
}
__device__ __forceinline__ void cp_wait1() {
    asm volatile("cp.async.wait_group 1;" ::: "memory");
}
__device__ __forceinline__ void cp_wait0() {
    asm volatile("cp.async.wait_group 0;" ::: "memory");
}
__device__ __forceinline__ void ldsm_x4(uint32_t* r, uint32_t a) {
    asm volatile("ldmatrix.sync.aligned.m8n8.x4.shared.b16 {%0,%1,%2,%3}, [%4];"
                 : "=r"(r[0]), "=r"(r[1]), "=r"(r[2]), "=r"(r[3]) : "r"(a));
}
__device__ __forceinline__ void ldsm_x4t(uint32_t* r, uint32_t a) {
    asm volatile("ldmatrix.sync.aligned.m8n8.x4.trans.shared.b16 {%0,%1,%2,%3}, [%4];"
                 : "=r"(r[0]), "=r"(r[1]), "=r"(r[2]), "=r"(r[3]) : "r"(a));
}
__device__ __forceinline__ void mma_bf16(float* d, const uint32_t* a,
                                         uint32_t b0, uint32_t b1) {
    asm volatile(
        "mma.sync.aligned.m16n8k16.row.col.f32.bf16.bf16.f32 "
        "{%0,%1,%2,%3}, {%4,%5,%6,%7}, {%8,%9}, {%0,%1,%2,%3};"
        : "+f"(d[0]), "+f"(d[1]), "+f"(d[2]), "+f"(d[3])
        : "r"(a[0]), "r"(a[1]), "r"(a[2]), "r"(a[3]), "r"(b0), "r"(b1));
}
__device__ __forceinline__ uint32_t pack2(float a, float b) {
    __nv_bfloat162 t;
    t.x = __float2bfloat16_rn(a); t.y = __float2bfloat16_rn(b);
    return *(uint32_t*)&t;
}
__device__ __forceinline__ void split2(float a, float b, uint32_t& h, uint32_t& l) {
    __nv_bfloat16 ha = __float2bfloat16_rn(a), hb = __float2bfloat16_rn(b);
    h = pack2(a, b);
    l = pack2(a - __bfloat162float(ha), b - __bfloat162float(hb));
}

// ------------------------------ prep kernels -------------------------------
__global__ void split_x(const float* __restrict__ src) {
    const size_t i = ((size_t)blockIdx.x * blockDim.x + threadIdx.x) * 4;
    const float4 v = *(const float4*)(src + i);
    uint32_t h0, l0, h1, l1;
    split2(v.x, v.y, h0, l0);
    split2(v.z, v.w, h1, l1);
    *(uint32_t*)(g_xh + i)     = h0;
    *(uint32_t*)(g_xh + i + 2) = h1;
    *(uint32_t*)(g_xl + i)     = l0;
    *(uint32_t*)(g_xl + i + 2) = l1;
}

__global__ void transpose_qkv(const float* __restrict__ W) {
    __shared__ float t[32][33];
    const int c0 = blockIdx.x * 32, k0 = blockIdx.y * 32;
    const int tx = threadIdx.x, ty = threadIdx.y;
    #pragma unroll
    for (int i = 0; i < 32; i += 8)
        t[ty + i][tx] = W[(size_t)(k0 + ty + i) * 1536 + c0 + tx];
    __syncthreads();
    #pragma unroll
    for (int i = 0; i < 32; i += 8) {
        const int c  = c0 + ty + i;
        const int hd = c / 192, rr = c - hd * 192;
        const int cp = (rr >> 6) * 512 + hd * 64 + (rr & 63);
        const float v = t[tx][ty + i];
        const __nv_bfloat16 h = __float2bfloat16_rn(v);
        g_wtq_hi[(size_t)cp * 512 + k0 + tx] = h;
        g_wtq_lo[(size_t)cp * 512 + k0 + tx] =
            __float2bfloat16_rn(v - __bfloat162float(h));
    }
}

__global__ void transpose_proj(const float* __restrict__ W) {
    __shared__ float t[32][33];
    const int c0 = blockIdx.x * 32, k0 = blockIdx.y * 32;
    const int tx = threadIdx.x, ty = threadIdx.y;
    #pragma unroll
    for (int i = 0; i < 32; i += 8)
        t[ty + i][tx] = W[(size_t)(k0 + ty + i) * 512 + c0 + tx];
    __syncthreads();
    #pragma unroll
    for (int i = 0; i < 32; i += 8) {
        const int c = c0 + ty + i;
        const float v = t[tx][ty + i];
        const __nv_bfloat16 h = __float2bfloat16_rn(v);
        g_wtp_hi[(size_t)c * 512 + k0 + tx] = h;
        g_wtp_lo[(size_t)c * 512 + k0 + tx] =
            __float2bfloat16_rn(v - __bfloat162float(h));
    }
}

__global__ void perm_bias(const float* __restrict__ b) {
    const int c = blockIdx.x * 512 + threadIdx.x;
    if (c < 1536) {
        const int hd = c / 192, rr = c - hd * 192;
        g_bq[(rr >> 6) * 512 + hd * 64 + (rr & 63)] = b[c];
    }
}

// ---------------------------------------------------------------------------
// bf16 split GEMM. B hi/lo fragments fetched with ONE ldmatrix.x4 per nt
// (lanes 0-15 -> hi rows, lanes 16-31 -> lo rows).
// ---------------------------------------------------------------------------
static constexpr int GS      = 40;
static constexpr int MAT_B   = 128 * GS * 2;
static constexpr int BUF_B   = 4 * MAT_B;
static constexpr int GT_SMEM = 2 * BUF_B + 512;

template <int MODE>
__global__ void __launch_bounds__(256, 2)
gemm_mma(const float* __restrict__ bias, float* __restrict__ Cout)
{
    extern __shared__ char smem[];
    const uint32_t sb = smem_u32(smem);
    float* sbias = (float*)(smem + 2 * BUF_B);

    const int tid = threadIdx.x, wid = tid >> 5, lane = tid & 31;
    const int wm = wid >> 2, wn = wid & 3;
    const int n0 = blockIdx.x * 128, m0g = blockIdx.y * 128;

    const __nv_bfloat16* Ah = (MODE == 1) ? g_xh : g_oh;
    const __nv_bfloat16* Al = (MODE == 1) ? g_xl : g_ol;
    const __nv_bfloat16* Bh = (MODE == 1) ? g_wtq_hi : g_wtp_hi;
    const __nv_bfloat16* Bl = (MODE == 1) ? g_wtq_lo : g_wtp_lo;

    if (tid < 128) {
        const float* bptr = (MODE == 1) ? (const float*)g_bq : bias;
        sbias[tid] = bptr[n0 + tid];
    }

    const auto issue = [&](int kt, int buf) {
        const int kc = kt << 5;
        #pragma unroll
        for (int p = 0; p < 8; ++p) {
            const int idx = tid + (p << 8);
            const int mat = idx >> 9;
            const int rem = idx & 511;
            const int r = rem >> 2, f = (rem & 3) << 3;
            const __nv_bfloat16* src;
            if      (mat == 0) src = Ah + (size_t)(m0g + r) * 512 + kc + f;
            else if (mat == 1) src = Al + (size_t)(m0g + r) * 512 + kc + f;
            else if (mat == 2) src = Bh + (size_t)(n0  + r) * 512 + kc + f;
            else               src = Bl + (size_t)(n0  + r) * 512 + kc + f;
            cp_async16(sb + buf * BUF_B + mat * MAT_B + r * (GS * 2) + f * 2, src);
        }
        cp_commit();
    };

    float acc[4][4][4];
    #pragma unroll
    for (int i = 0; i < 4; ++i)
        #pragma unroll
        for (int j = 0; j < 4; ++j)
            #pragma unroll
            for (int z = 0; z < 4; ++z) acc[i][j][z] = 0.f;

    issue(0, 0);
    for (int kt = 0; kt < 16; ++kt) {
        const int cur = kt & 1;
        if (kt + 1 < 16) { issue(kt + 1, cur ^ 1); cp_wait1(); }
        else             { cp_wait0(); }
        __syncthreads();

        const uint32_t base = sb + cur * BUF_B;
        #pragma unroll
        for (int k16 = 0; k16 < 32; k16 += 16) {
            uint32_t ah[4][4], al[4][4];
            #pragma unroll
            for (int mt = 0; mt < 4; ++mt) {
                const uint32_t a = base
                    + (uint32_t)((wm * 64 + mt * 16 + (lane & 15)) * (GS * 2))
                    + (uint32_t)((k16 + ((lane >> 4) << 3)) * 2);
                ldsm_x4(ah[mt], a);
                ldsm_x4(al[mt], a + MAT_B);
            }
            #pragma unroll
            for (int nt = 0; nt < 4; ++nt) {
                // paired hi/lo B fetch: lanes 0-15 hi, 16-31 lo
                uint32_t b4[4];
                const uint32_t ba = base + 2 * MAT_B
                    + (uint32_t)((lane < 16) ? 0 : MAT_B)
                    + (uint32_t)((wn * 32 + nt * 8 + (lane & 7)) * (GS * 2))
                    + (uint32_t)((k16 + (((lane >> 3) & 1) << 3)) * 2);
                ldsm_x4(b4, ba);
                #pragma unroll
                for (int mt = 0; mt < 4; ++mt) {
                    mma_bf16(acc[mt][nt], ah[mt], b4[0], b4[1]);
                    mma_bf16(acc[mt][nt], ah[mt], b4[2], b4[3]);
                    mma_bf16(acc[mt][nt], al[mt], b4[0], b4[1]);
                }
            }
        }
        __syncthreads();
    }

    __nv_bfloat16 *dh = nullptr, *dl = nullptr;
    int col0 = n0;
    if (MODE == 1) {
        const int seg = n0 >> 9;
        dh = (seg == 0) ? g_qh : (seg == 1) ? g_kh : g_vh;
        dl = (seg == 0) ? g_ql : (seg == 1) ? g_kl : g_vl;
        col0 = n0 & 511;
    }
    #pragma unroll
    for (int mt = 0; mt < 4; ++mt) {
        #pragma unroll
        for (int nt = 0; nt < 4; ++nt) {
            const int cb = wn * 32 + nt * 8 + (lane & 3) * 2;
            const int r0 = m0g + wm * 64 + mt * 16 + (lane >> 2);
            const float b0 = sbias[cb], b1 = sbias[cb + 1];
            const float v00 = acc[mt][nt][0] + b0, v01 = acc[mt][nt][1] + b1;
            const float v10 = acc[mt][nt][2] + b0, v11 = acc[mt][nt][3] + b1;
            if (MODE == 1) {
                uint32_t h0, l0, h1, l1;
                split2(v00, v01, h0, l0);
                split2(v10, v11, h1, l1);
                *(uint32_t*)(dh + (size_t)r0 * 512 + col0 + cb)       = h0;
                *(uint32_t*)(dl + (size_t)r0 * 512 + col0 + cb)       = l0;
                *(uint32_t*)(dh + (size_t)(r0 + 8) * 512 + col0 + cb) = h1;
                *(uint32_t*)(dl + (size_t)(r0 + 8) * 512 + col0 + cb) = l1;
            } else {
                float2 f0; f0.x = v00; f0.y = v01;
                float2 f1; f1.x = v10; f1.y = v11;
                *(float2*)(Cout + (size_t)r0 * 512 + col0 + cb)       = f0;
                *(float2*)(Cout + (size_t)(r0 + 8) * 512 + col0 + cb) = f1;
            }
        }
    }
}

// ---------------------------------------------------------------------------
// Flash banded attention on mma.sync (bf16 hi/lo), paired-x4 K and V fetches.
// CTA: one (b,s), 32 query blocks; key chunks of 32; 8 warps.
// ---------------------------------------------------------------------------
static constexpr int ARS   = 1040;
static constexpr int AT_QH = 0;
static constexpr int AT_QL = AT_QH + 32 * ARS;
static constexpr int AT_KH = AT_QL + 32 * ARS;
static constexpr int AT_KL = AT_KH + 32 * ARS;
static constexpr int AT_VH = AT_KL + 32 * ARS;
static constexpr int AT_VL = AT_VH + 32 * ARS;
static constexpr int AT_PH = AT_VL + 32 * ARS;
static constexpr int AT_PL = AT_PH + 32 * 80;
static constexpr int AT_M  = AT_PL + 32 * 80;
static constexpr int AT_L  = AT_M + 128;
static constexpr int AT_C  = AT_L + 128;
static constexpr int AT_PM = AT_C + 128;
static constexpr int AT_PS = AT_PM + 512;
static constexpr int AT_SMEM = AT_PS + 512;

__global__ void __launch_bounds__(256, 1)
attn_mma()
{
    extern __shared__ char smem[];
    const uint32_t sb = smem_u32(smem);
    float* sM  = (float*)(smem + AT_M);
    float* sL  = (float*)(smem + AT_L);
    float* sC  = (float*)(smem + AT_C);
    float* sPM = (float*)(smem + AT_PM);
    float* sPS = (float*)(smem + AT_PS);

    const int tid = threadIdx.x, wid = tid >> 5, lane = tid & 31;
    const int qh = wid & 1, ws = wid >> 1;
    const int g = lane >> 2, t = lane & 3;
    const int i0 = blockIdx.x * 32;
    const int s  = blockIdx.y;
    const int bb = blockIdx.z * N_;

    if (tid < 32) { sM[tid] = -1e30f; sL[tid] = 0.f; }

    const int jlo = (i0 - 64 > 0) ? i0 - 64 : 0;
    const int jhe = (i0 + 96 < 256) ? i0 + 96 : 256;
    const int nc  = (jhe - jlo) >> 5;

    const auto load2 = [&](int blk0, uint32_t dh, uint32_t dl,
                           const __nv_bfloat16* gh, const __nv_bfloat16* gl) {
        #pragma unroll
        for (int p = 0; p < 16; ++p) {
            const int idx = tid + (p << 8);
            const int mat = idx >> 11;
            const int rem = idx & 2047;
            const int r = rem >> 6, f = rem & 63;
            const __nv_bfloat16* src = (mat ? gl : gh)
                + ((size_t)(bb + (blk0 + r) * 32 + s) * 512 + f * 8);
            cp_async16((mat ? dl : dh) + r * ARS + f * 16, src);
        }
    };

    load2(i0,  sb + AT_QH, sb + AT_QL, g_qh, g_ql);
    load2(jlo, sb + AT_KH, sb + AT_KL, g_kh, g_kl);
    cp_commit();
    load2(jlo, sb + AT_VH, sb + AT_VL, g_vh, g_vl);
    cp_commit();

    float acc[16][4];
    #pragma unroll
    for (int nt = 0; nt < 16; ++nt)
        #pragma unroll
        for (int z = 0; z < 4; ++z) acc[nt][z] = 0.f;

    const int lr0 = qh * 16 + g, lr1 = lr0 + 8;
    const int gq0 = i0 + lr0, gq1 = i0 + lr1;

    for (int n = 0; n < nc; ++n) {
        const int jc = jlo + n * 32;
        cp_wait1();
        __syncthreads();

        // ---- QK ----
        float sc[4] = {0.f, 0.f, 0.f, 0.f};
        {
            const uint32_t qa = sb + AT_QH + (qh * 16 + (lane & 15)) * ARS
                              + ((lane >> 4) << 4);
            // paired hi/lo K: lanes 0-15 hi, 16-31 lo
            const uint32_t ka = sb + ((lane < 16) ? AT_KH : AT_KL)
                              + (ws * 8 + (lane & 7)) * ARS
                              + (((lane >> 3) & 1) << 4);
            #pragma unroll 8
            for (int kc = 0; kc < 32; ++kc) {
                uint32_t ah[4], al[4], kb[4];
                ldsm_x4(ah, qa + kc * 32);
                ldsm_x4(al, qa + kc * 32 + (AT_QL - AT_QH));
                ldsm_x4(kb, ka + kc * 32);
                mma_bf16(sc, ah, kb[0], kb[1]);
                mma_bf16(sc, ah, kb[2], kb[3]);
                mma_bf16(sc, al, kb[0], kb[1]);
            }
        }

        const int cj = jc + ws * 8 + 2 * t;
        const bool m00 = (cj     >= gq0 - 64) && (cj     <= gq0 + 64);
        const bool m01 = (cj + 1 >= gq0 - 64) && (cj + 1 <= gq0 + 64);
        const bool m10 = (cj     >= gq1 - 64) && (cj     <= gq1 + 64);
        const bool m11 = (cj + 1 >= gq1 - 64) && (cj + 1 <= gq1 + 64);
        const float s00 = m00 ? sc[0] * 0.125f : -1e30f;
        const float s01 = m01 ? sc[1] * 0.125f : -1e30f;
        const float s10 = m10 ? sc[2] * 0.125f : -1e30f;
        const float s11 = m11 ? sc[3] * 0.125f : -1e30f;

        float x0 = fmaxf(s00, s01), x1 = fmaxf(s10, s11);
        x0 = fmaxf(x0, __shfl_xor_sync(0xffffffffu, x0, 1));
        x0 = fmaxf(x0, __shfl_xor_sync(0xffffffffu, x0, 2));
        x1 = fmaxf(x1, __shfl_xor_sync(0xffffffffu, x1, 1));
        x1 = fmaxf(x1, __shfl_xor_sync(0xffffffffu, x1, 2));
        if (t == 0) { sPM[lr0 * 4 + ws] = x0; sPM[lr1 * 4 + ws] = x1; }
        __syncthreads();

        if (n + 1 < nc) { load2(jc + 32, sb + AT_KH, sb + AT_KL, g_kh, g_kl); cp_commit(); }

        if (tid < 32) {
            const float mo = sM[tid];
            float mn = fmaxf(fmaxf(sPM[tid * 4], sPM[tid * 4 + 1]),
                             fmaxf(sPM[tid * 4 + 2], sPM[tid * 4 + 3]));
            mn = fmaxf(mn, mo);
            sM[tid] = mn;
            sC[tid] = __expf(mo - mn);
        }
        __syncthreads();

        const float mn0 = sM[lr0], mn1 = sM[lr1];
        const float p00 = m00 ? __expf(s00 - mn0) : 0.f;
        const float p01 = m01 ? __expf(s01 - mn0) : 0.f;
        const float p10 = m10 ? __expf(s10 - mn1) : 0.f;
        const float p11 = m11 ? __expf(s11 - mn1) : 0.f;
        {
            uint32_t h0, l0, h1, l1;
            split2(p00, p01, h0, l0);
            split2(p10, p11, h1, l1);
            const uint32_t cb = (uint32_t)((ws * 8 + 2 * t) * 2);
            *(uint32_t*)(smem + AT_PH + lr0 * 80 + cb) = h0;
            *(uint32_t*)(smem + AT_PL + lr0 * 80 + cb) = l0;
            *(uint32_t*)(smem + AT_PH + lr1 * 80 + cb) = h1;
            *(uint32_t*)(smem + AT_PL + lr1 * 80 + cb) = l1;
        }
        float r0s = p00 + p01, r1s = p10 + p11;
        r0s += __shfl_xor_sync(0xffffffffu, r0s, 1);
        r0s += __shfl_xor_sync(0xffffffffu, r0s, 2);
        r1s += __shfl_xor_sync(0xffffffffu, r1s, 1);
        r1s += __shfl_xor_sync(0xffffffffu, r1s, 2);
        if (t == 0) { sPS[lr0 * 4 + ws] = r0s; sPS[lr1 * 4 + ws] = r1s; }

        if (n + 1 == nc) cp_wait0(); else cp_wait1();
        __syncthreads();

        if (tid < 32)
            sL[tid] = sL[tid] * sC[tid]
                    + sPS[tid * 4] + sPS[tid * 4 + 1]
                    + sPS[tid * 4 + 2] + sPS[tid * 4 + 3];

        // ---- PV ----
        const float cr0 = sC[lr0], cr1 = sC[lr1];
        #pragma unroll
        for (int nt = 0; nt < 16; ++nt) {
            acc[nt][0] *= cr0; acc[nt][1] *= cr0;
            acc[nt][2] *= cr1; acc[nt][3] *= cr1;
        }
        {
            const uint32_t pa = sb + AT_PH + (qh * 16 + (lane & 15)) * 80
                              + ((lane >> 4) << 4);
            // paired hi/lo V (trans): lanes 0-15 hi, 16-31 lo
            const uint32_t va = sb + ((lane < 16) ? AT_VH : AT_VL)
                              + (lane & 15) * ARS + (uint32_t)(ws * 256);
            #pragma unroll
            for (int k2 = 0; k2 < 2; ++k2) {
                uint32_t ph[4], pl[4];
                ldsm_x4(ph, pa + k2 * 32);
                ldsm_x4(pl, pa + k2 * 32 + (AT_PL - AT_PH));
                #pragma unroll
                for (int nt = 0; nt < 16; ++nt) {
                    uint32_t vv[4];
                    ldsm_x4t(vv, va + (uint32_t)(k2 * 16 * ARS) + nt * 16);
                    mma_bf16(acc[nt], ph, vv[0], vv[1]);
                    mma_bf16(acc[nt], ph, vv[2], vv[3]);
                    mma_bf16(acc[nt], pl, vv[0], vv[1]);
                }
            }
        }
        __syncthreads();

        if (n + 1 < nc) { load2(jc + 32, sb + AT_VH, sb + AT_VL, g_vh, g_vl); cp_commit(); }
    }

    __syncthreads();
    const float inv0 = 1.f / sL[lr0], inv1 = 1.f / sL[lr1];
    const size_t tok0 = (size_t)(bb + gq0 * 32 + s) * 512;
    const size_t tok1 = (size_t)(bb + gq1 * 32 + s) * 512;
    #pragma unroll
    for (int nt = 0; nt < 16; ++nt) {
        const int c = ws * 128 + nt * 8 + 2 * t;
        uint32_t h0, l0, h1, l1;
        split2(acc[nt][0] * inv0, acc[nt][1] * inv0, h0, l0);
        split2(acc[nt][2] * inv1, acc[nt][3] * inv1, h1, l1);
        *(uint32_t*)(g_oh + tok0 + c) = h0;
        *(uint32_t*)(g_ol + tok0 + c) = l0;
        *(uint32_t*)(g_oh + tok1 + c) = h1;
        *(uint32_t*)(g_ol + tok1 + c) = l1;
    }
}

// ---------------------------------------------------------------------------
extern "C" void kernel_launch(void* const* d_in, const int* in_sizes, int n_in,
                              void* d_out, int out_size)
{
    const float* x     = (const float*)d_in[0];
    const float* Wqkv  = (const float*)d_in[1];
    const float* bqkv  = (const float*)d_in[2];
    const float* Wproj = (const float*)d_in[3];
    const float* bproj = (const float*)d_in[4];
    float*       out   = (float*)d_out;

    transpose_qkv <<<dim3(48, 16), dim3(32, 8)>>>(Wqkv);
    transpose_proj<<<dim3(16, 16), dim3(32, 8)>>>(Wproj);
    perm_bias<<<3, 512>>>(bqkv);
    split_x<<<TOK * C_ / 1024, 256>>>(x);

    cudaFuncSetAttribute(gemm_mma<1>, cudaFuncAttributeMaxDynamicSharedMemorySize, GT_SMEM);
    gemm_mma<1><<<dim3(12, 512), 256, GT_SMEM>>>(nullptr, nullptr);

    cudaFuncSetAttribute(attn_mma, cudaFuncAttributeMaxDynamicSharedMemorySize, AT_SMEM);
    attn_mma<<<dim3(8, 32, 8), 256, AT_SMEM>>>();

    cudaFuncSetAttribute(gemm_mma<2>, cudaFuncAttributeMaxDynamicSharedMemorySize, GT_SMEM);
    gemm_mma<2><<<dim3(4, 512), 256, GT_SMEM>>>(bproj, out);
}